// round 1
// baseline (speedup 1.0000x reference)
#include <cuda_runtime.h>

#define NPOS 786432            // D*W*H = 48*128*128
#define QSCALE 0.5946035575013605f   // 8^(-1/4)

// Scratch (201.3 MB each) — device globals, no allocation in kernel_launch.
__device__ float g_q[64u * 786432u];
__device__ float g_k[64u * 786432u];
__device__ float g_v[64u * 786432u];
__device__ float g_o[64u * 786432u];

// ---------------------------------------------------------------------------
// Kernel 1: fused QKV 1x1 conv.  Y[192, N] = W[192,64] @ X[64, N] + b
// rows 0-63 -> q (scaled), 64-127 -> k, 128-191 -> v.
// 256 threads, per-thread 12x8 register tile, 128 positions per CTA.
// smem: Ws[192][65] + bias[192] + Xs[64][132]
// ---------------------------------------------------------------------------
__global__ __launch_bounds__(256) void qkv_kernel(
    const float* __restrict__ x,
    const float* __restrict__ wq, const float* __restrict__ bq,
    const float* __restrict__ wk, const float* __restrict__ bk,
    const float* __restrict__ wv, const float* __restrict__ bv)
{
    extern __shared__ float sm[];
    float* Ws   = sm;              // 192*65 = 12480
    float* bias = Ws + 192 * 65;   // 192
    float* Xs   = bias + 192;      // 64*132 = 8448

    const int tid = threadIdx.x;
    for (int i = tid; i < 4096; i += 256) {
        int o = i >> 6, c = i & 63;
        Ws[o * 65 + c]         = wq[i];
        Ws[(o + 64) * 65 + c]  = wk[i];
        Ws[(o + 128) * 65 + c] = wv[i];
    }
    if (tid < 64) {
        bias[tid]       = bq[tid];
        bias[tid + 64]  = bk[tid];
        bias[tid + 128] = bv[tid];
    }
    const int p0 = blockIdx.x << 7;
    for (int i = tid; i < 8192; i += 256) {
        int c = i >> 7, p = i & 127;
        Xs[c * 132 + p] = x[c * NPOS + p0 + p];
    }
    __syncthreads();

    const int rg = tid >> 4;   // 0..15 -> 12 output rows each
    const int cg = tid & 15;   // 0..15 -> 8 positions each

    float acc[12][8];
#pragma unroll
    for (int i = 0; i < 12; i++)
#pragma unroll
        for (int j = 0; j < 8; j++) acc[i][j] = 0.f;

#pragma unroll 2
    for (int c = 0; c < 64; c++) {
        float4 b0 = *(const float4*)&Xs[c * 132 + cg * 8];
        float4 b1 = *(const float4*)&Xs[c * 132 + cg * 8 + 4];
        float bb[8] = {b0.x, b0.y, b0.z, b0.w, b1.x, b1.y, b1.z, b1.w};
#pragma unroll
        for (int i = 0; i < 12; i++) {
            float a = Ws[(rg * 12 + i) * 65 + c];
#pragma unroll
            for (int j = 0; j < 8; j++) acc[i][j] = fmaf(a, bb[j], acc[i][j]);
        }
    }

#pragma unroll
    for (int i = 0; i < 12; i++) {
        int o = rg * 12 + i;
        float bb = bias[o];
        float sc = (o < 64) ? QSCALE : 1.0f;
        float* dst;
        int oo;
        if (o < 64)       { dst = g_q; oo = o; }
        else if (o < 128) { dst = g_k; oo = o - 64; }
        else              { dst = g_v; oo = o - 128; }
        float4 v0, v1;
        v0.x = (acc[i][0] + bb) * sc; v0.y = (acc[i][1] + bb) * sc;
        v0.z = (acc[i][2] + bb) * sc; v0.w = (acc[i][3] + bb) * sc;
        v1.x = (acc[i][4] + bb) * sc; v1.y = (acc[i][5] + bb) * sc;
        v1.z = (acc[i][6] + bb) * sc; v1.w = (acc[i][7] + bb) * sc;
        *(float4*)&dst[oo * NPOS + p0 + cg * 8]     = v0;
        *(float4*)&dst[oo * NPOS + p0 + cg * 8 + 4] = v1;
    }
}

// ---------------------------------------------------------------------------
// Kernel 2: per-(c,d)-slice attention over [W=128, H=128].
// One CTA per slice (3072). 128 threads (4 warps, one per SMSP).
// smem: KsT[128h][132w] + Vs[128k][128h] + QsT[128h][68w] + PsT[128k][68w]
// pitches 132/68: 16B-aligned float4 reads, <=4-way conflicted transposed writes.
// Q-block = 64 rows (2 blocks). Per-thread 8x8 register tiles.
// ---------------------------------------------------------------------------
__global__ __launch_bounds__(128) void attn_kernel()
{
    extern __shared__ float sm[];
    float* KsT = sm;                  // 128*132 = 16896
    float* Vs  = KsT + 128 * 132;     // 128*128 = 16384
    float* QsT = Vs + 128 * 128;      // 128*68  = 8704
    float* PsT = QsT + 128 * 68;      // 128*68  = 8704

    const int slice = blockIdx.x;     // c*48 + d
    const int base  = slice * 16384;
    const float* Qg = g_q + base;
    const float* Kg = g_k + base;
    const float* Vg = g_v + base;
    float*       Og = g_o + base;

    const int tid = threadIdx.x;
    for (int i = tid; i < 16384; i += 128) {
        int w = i >> 7, h = i & 127;
        KsT[h * 132 + w] = Kg[i];
        Vs[i] = Vg[i];
    }

    const int rg = tid >> 4;   // 0..7 : 8 q-rows each
    const int cg = tid & 15;   // 0..15: 8 cols each

    for (int blk = 0; blk < 2; blk++) {
        __syncthreads();  // K/V ready (blk 0); PsT reads done (blk 1)
        for (int i = tid; i < 8192; i += 128) {
            int wl = i >> 7, h = i & 127;
            QsT[h * 68 + wl] = Qg[(blk * 64 + wl) * 128 + h];
        }
        __syncthreads();

        // ---- S = Q Kt : per-thread 8x8 tile, contraction over h ----
        float s[8][8];
#pragma unroll
        for (int i = 0; i < 8; i++)
#pragma unroll
            for (int j = 0; j < 8; j++) s[i][j] = 0.f;

#pragma unroll 2
        for (int h = 0; h < 128; h++) {
            float4 q0 = *(const float4*)&QsT[h * 68 + rg * 8];
            float4 q1 = *(const float4*)&QsT[h * 68 + rg * 8 + 4];
            float4 k0 = *(const float4*)&KsT[h * 132 + cg * 8];
            float4 k1 = *(const float4*)&KsT[h * 132 + cg * 8 + 4];
            float qv[8] = {q0.x, q0.y, q0.z, q0.w, q1.x, q1.y, q1.z, q1.w};
            float kv[8] = {k0.x, k0.y, k0.z, k0.w, k1.x, k1.y, k1.z, k1.w};
#pragma unroll
            for (int i = 0; i < 8; i++)
#pragma unroll
                for (int j = 0; j < 8; j++)
                    s[i][j] = fmaf(qv[i], kv[j], s[i][j]);
        }

        // ---- row softmax: reduce across 16 cg lanes (half-warp) ----
        float rinv[8];
#pragma unroll
        for (int i = 0; i < 8; i++) {
            float m = s[i][0];
#pragma unroll
            for (int j = 1; j < 8; j++) m = fmaxf(m, s[i][j]);
            for (int o = 1; o < 16; o <<= 1)
                m = fmaxf(m, __shfl_xor_sync(0xffffffffu, m, o));
            float sum = 0.f;
#pragma unroll
            for (int j = 0; j < 8; j++) {
                s[i][j] = __expf(s[i][j] - m);
                sum += s[i][j];
            }
            for (int o = 1; o < 16; o <<= 1)
                sum += __shfl_xor_sync(0xffffffffu, sum, o);
            rinv[i] = 1.0f / sum;
        }

        // ---- write P transposed: PsT[k][w_local] ----
#pragma unroll
        for (int j = 0; j < 8; j++) {
            float4 p0 = make_float4(s[0][j], s[1][j], s[2][j], s[3][j]);
            float4 p1 = make_float4(s[4][j], s[5][j], s[6][j], s[7][j]);
            *(float4*)&PsT[(cg * 8 + j) * 68 + rg * 8]     = p0;
            *(float4*)&PsT[(cg * 8 + j) * 68 + rg * 8 + 4] = p1;
        }
        __syncthreads();

        // ---- O = P @ V : contraction over k ----
        float oa[8][8];
#pragma unroll
        for (int i = 0; i < 8; i++)
#pragma unroll
            for (int j = 0; j < 8; j++) oa[i][j] = 0.f;

#pragma unroll 2
        for (int k = 0; k < 128; k++) {
            float4 p0 = *(const float4*)&PsT[k * 68 + rg * 8];
            float4 p1 = *(const float4*)&PsT[k * 68 + rg * 8 + 4];
            float4 v0 = *(const float4*)&Vs[k * 128 + cg * 8];
            float4 v1 = *(const float4*)&Vs[k * 128 + cg * 8 + 4];
            float pv[8] = {p0.x, p0.y, p0.z, p0.w, p1.x, p1.y, p1.z, p1.w};
            float vv[8] = {v0.x, v0.y, v0.z, v0.w, v1.x, v1.y, v1.z, v1.w};
#pragma unroll
            for (int i = 0; i < 8; i++)
#pragma unroll
                for (int j = 0; j < 8; j++)
                    oa[i][j] = fmaf(pv[i], vv[j], oa[i][j]);
        }

#pragma unroll
        for (int i = 0; i < 8; i++) {
            int w = blk * 64 + rg * 8 + i;
            float r = rinv[i];
            float4 o0 = make_float4(oa[i][0] * r, oa[i][1] * r, oa[i][2] * r, oa[i][3] * r);
            float4 o1 = make_float4(oa[i][4] * r, oa[i][5] * r, oa[i][6] * r, oa[i][7] * r);
            *(float4*)&Og[w * 128 + cg * 8]     = o0;
            *(float4*)&Og[w * 128 + cg * 8 + 4] = o1;
        }
    }
}

// ---------------------------------------------------------------------------
// Kernel 3: output 1x1 conv.  out[64, N] = Wo[64,64] @ O[64, N] + bo
// 256 threads, per-thread 4x8 tile.
// smem: Ws[64][65] + bias[64] + Xs[64][132]
// ---------------------------------------------------------------------------
__global__ __launch_bounds__(256) void out_kernel(
    const float* __restrict__ wo, const float* __restrict__ bo,
    float* __restrict__ out)
{
    extern __shared__ float sm[];
    float* Ws   = sm;             // 64*65 = 4160
    float* bias = Ws + 64 * 65;   // 64
    float* Xs   = bias + 64;      // 64*132

    const int tid = threadIdx.x;
    for (int i = tid; i < 4096; i += 256) {
        int o = i >> 6, c = i & 63;
        Ws[o * 65 + c] = wo[i];
    }
    if (tid < 64) bias[tid] = bo[tid];
    const int p0 = blockIdx.x << 7;
    for (int i = tid; i < 8192; i += 256) {
        int c = i >> 7, p = i & 127;
        Xs[c * 132 + p] = g_o[c * NPOS + p0 + p];
    }
    __syncthreads();

    const int rg = tid >> 4, cg = tid & 15;
    float acc[4][8];
#pragma unroll
    for (int i = 0; i < 4; i++)
#pragma unroll
        for (int j = 0; j < 8; j++) acc[i][j] = 0.f;

#pragma unroll 4
    for (int c = 0; c < 64; c++) {
        float4 b0 = *(const float4*)&Xs[c * 132 + cg * 8];
        float4 b1 = *(const float4*)&Xs[c * 132 + cg * 8 + 4];
        float bb[8] = {b0.x, b0.y, b0.z, b0.w, b1.x, b1.y, b1.z, b1.w};
#pragma unroll
        for (int i = 0; i < 4; i++) {
            float a = Ws[(rg * 4 + i) * 65 + c];
#pragma unroll
            for (int j = 0; j < 8; j++) acc[i][j] = fmaf(a, bb[j], acc[i][j]);
        }
    }

#pragma unroll
    for (int i = 0; i < 4; i++) {
        int o = rg * 4 + i;
        float bb = bias[o];
        float4 v0 = make_float4(acc[i][0] + bb, acc[i][1] + bb, acc[i][2] + bb, acc[i][3] + bb);
        float4 v1 = make_float4(acc[i][4] + bb, acc[i][5] + bb, acc[i][6] + bb, acc[i][7] + bb);
        *(float4*)&out[o * NPOS + p0 + cg * 8]     = v0;
        *(float4*)&out[o * NPOS + p0 + cg * 8 + 4] = v1;
    }
}

// ---------------------------------------------------------------------------
extern "C" void kernel_launch(void* const* d_in, const int* in_sizes, int n_in,
                              void* d_out, int out_size)
{
    const float* x  = (const float*)d_in[0];
    const float* wq = (const float*)d_in[1];
    const float* bq = (const float*)d_in[2];
    const float* wk = (const float*)d_in[3];
    const float* bk = (const float*)d_in[4];
    const float* wv = (const float*)d_in[5];
    const float* bv = (const float*)d_in[6];
    const float* wo = (const float*)d_in[7];
    const float* bo = (const float*)d_in[8];
    float* out = (float*)d_out;

    const int smem1 = (192 * 65 + 192 + 64 * 132) * 4;                     // 84480
    const int smem2 = (128 * 132 + 128 * 128 + 128 * 68 + 128 * 68) * 4;  // 202752
    const int smem3 = (64 * 65 + 64 + 64 * 132) * 4;                      // 50688

    cudaFuncSetAttribute(qkv_kernel,  cudaFuncAttributeMaxDynamicSharedMemorySize, smem1);
    cudaFuncSetAttribute(attn_kernel, cudaFuncAttributeMaxDynamicSharedMemorySize, smem2);
    cudaFuncSetAttribute(out_kernel,  cudaFuncAttributeMaxDynamicSharedMemorySize, smem3);

    qkv_kernel<<<NPOS / 128, 256, smem1>>>(x, wq, bq, wk, bk, wv, bv);
    attn_kernel<<<64 * 48, 128, smem2>>>();
    out_kernel<<<NPOS / 128, 256, smem3>>>(wo, bo, out);
}

// round 2
// speedup vs baseline: 1.4360x; 1.4360x over previous
#include <cuda_runtime.h>

typedef unsigned long long u64;

#define NPOS 786432              // D*W*H = 48*128*128
#define QSCALE 0.5946035575013605f   // 8^(-1/4)

// Scratch — device globals (no allocation in kernel_launch).
__device__ float g_q[64u * 786432u];
__device__ float g_k[64u * 786432u];
__device__ float g_v[64u * 786432u];
__device__ float g_o[64u * 786432u];

// ---- f32x2 packed helpers (Blackwell FFMA2; ptxas never auto-fuses) ----
__device__ __forceinline__ u64 bcast2(float x) {
    u64 r;
    asm("mov.b64 %0, {%1, %1};" : "=l"(r) : "f"(x));
    return r;
}
__device__ __forceinline__ void ffma2(u64& d, u64 a, u64 b) {
    asm("fma.rn.f32x2 %0, %1, %2, %0;" : "+l"(d) : "l"(a), "l"(b));
}

// Accumulator: 16 rows x 4 cols per thread, rows packed in pairs.
// element(row r, col j) = f[(r>>1)*8 + j*2 + (r&1)]
#define ACC_F(A, r, j) (A).f[(((r) >> 1) * 8) + ((j) * 2) + ((r) & 1)]

// ---------------------------------------------------------------------------
// Kernel 1: fused QKV 1x1 conv.  Y[192,N] = W[192,64] @ X[64,N] + b
// 384 threads. rg = tid>>5 (12 groups x 16 rows), cg = tid&31 (32 x 4 cols).
// W stored transposed in smem so row-pairs load as packed u64 (no bcast).
// ---------------------------------------------------------------------------
__global__ __launch_bounds__(384) void qkv_kernel(
    const float* __restrict__ x,
    const float* __restrict__ wq, const float* __restrict__ bq,
    const float* __restrict__ wk, const float* __restrict__ bk,
    const float* __restrict__ wv, const float* __restrict__ bv)
{
    extern __shared__ float sm[];
    float* WsT  = sm;               // [64][196]  WsT[c*196 + o]
    float* bias = WsT + 64 * 196;   // 192
    float* Xs   = bias + 192;       // [64][132]

    const int tid = threadIdx.x;
    for (int i = tid; i < 4096; i += 384) {
        int o = i >> 6, c = i & 63;
        WsT[c * 196 + o]       = wq[i];
        WsT[c * 196 + o + 64]  = wk[i];
        WsT[c * 196 + o + 128] = wv[i];
    }
    if (tid < 64) { bias[tid] = bq[tid]; bias[tid + 64] = bk[tid]; bias[tid + 128] = bv[tid]; }
    const int p0 = blockIdx.x << 7;
    for (int i = tid; i < 8192; i += 384) {
        int c = i >> 7, p = i & 127;
        Xs[c * 132 + p] = x[c * NPOS + p0 + p];
    }
    __syncthreads();

    const int rg = tid >> 5;   // 0..11  -> rows rg*16 .. rg*16+15
    const int cg = tid & 31;   // 0..31  -> cols cg*4 .. cg*4+3

    union { u64 u[8][4]; float f[64]; } A;
#pragma unroll
    for (int ip = 0; ip < 8; ip++)
#pragma unroll
        for (int j = 0; j < 4; j++) A.u[ip][j] = 0ull;

#pragma unroll 2
    for (int c = 0; c < 64; c++) {
        const ulonglong2* wp = (const ulonglong2*)&WsT[c * 196 + rg * 16];
        ulonglong2 w0 = wp[0], w1 = wp[1], w2 = wp[2], w3 = wp[3];
        u64 wb[8] = { w0.x, w0.y, w1.x, w1.y, w2.x, w2.y, w3.x, w3.y };
        float4 x4 = *(const float4*)&Xs[c * 132 + cg * 4];
        u64 xb0 = bcast2(x4.x), xb1 = bcast2(x4.y), xb2 = bcast2(x4.z), xb3 = bcast2(x4.w);
#pragma unroll
        for (int ip = 0; ip < 8; ip++) {
            ffma2(A.u[ip][0], wb[ip], xb0);
            ffma2(A.u[ip][1], wb[ip], xb1);
            ffma2(A.u[ip][2], wb[ip], xb2);
            ffma2(A.u[ip][3], wb[ip], xb3);
        }
    }

#pragma unroll
    for (int r = 0; r < 16; r++) {
        int o = rg * 16 + r;
        float bb = bias[o];
        float sc = (o < 64) ? QSCALE : 1.0f;
        float* dst; int oo;
        if (o < 64)       { dst = g_q; oo = o; }
        else if (o < 128) { dst = g_k; oo = o - 64; }
        else              { dst = g_v; oo = o - 128; }
        float4 v;
        v.x = (ACC_F(A, r, 0) + bb) * sc;
        v.y = (ACC_F(A, r, 1) + bb) * sc;
        v.z = (ACC_F(A, r, 2) + bb) * sc;
        v.w = (ACC_F(A, r, 3) + bb) * sc;
        *(float4*)&dst[(size_t)oo * NPOS + p0 + cg * 4] = v;
    }
}

// ---------------------------------------------------------------------------
// Kernel 2: per-(c,d)-slice attention over [W=128, H=128]. One CTA per slice.
// 256 threads: half = tid>>7 handles Q rows [half*64, half*64+64).
// Per half-thread: rg = htid>>5 (4 x 16 rows), cg = htid&31 (32 x 4 cols).
// smem: KsT[128][132] + Vs[128][128] + QP[2][128][68] (Q^T then aliased P^T).
// Named barriers (id half+1, 128 threads) fence the QsT->PsT alias per half.
// ---------------------------------------------------------------------------
__global__ __launch_bounds__(256) void attn_kernel()
{
    extern __shared__ float sm[];
    float* KsT = sm;                  // 128*132
    float* Vs  = KsT + 128 * 132;     // 128*128
    float* QP  = Vs + 128 * 128;      // 2 * 128*68

    const int slice = blockIdx.x;     // c*48 + d
    const size_t base = (size_t)slice * 16384;
    const float* Qg = g_q + base;
    const float* Kg = g_k + base;
    const float* Vg = g_v + base;
    float*       Og = g_o + base;

    const int tid = threadIdx.x;
    for (int i = tid; i < 16384; i += 256) {
        int w = i >> 7, h = i & 127;
        KsT[h * 132 + w] = Kg[i];
        Vs[i] = Vg[i];
    }
    const int half = tid >> 7, htid = tid & 127;
    float* Qh = QP + half * (128 * 68);
    for (int i = htid; i < 8192; i += 128) {
        int wl = i >> 7, h = i & 127;
        Qh[h * 68 + wl] = Qg[(half * 64 + wl) * 128 + h];
    }
    __syncthreads();

    const int rg = htid >> 5;   // 0..3  -> rows rg*16..+15 (within half)
    const int cg = htid & 31;   // 0..31 -> cols cg*4..+3

    // ---- S = Q K^T (contraction over h). Rows packed as u64 pairs. ----
    union { u64 u[8][4]; float f[64]; } S;
#pragma unroll
    for (int ip = 0; ip < 8; ip++)
#pragma unroll
        for (int j = 0; j < 4; j++) S.u[ip][j] = 0ull;

#pragma unroll 2
    for (int h = 0; h < 128; h++) {
        const ulonglong2* qp = (const ulonglong2*)&Qh[h * 68 + rg * 16];
        ulonglong2 q0 = qp[0], q1 = qp[1], q2 = qp[2], q3 = qp[3];
        u64 qb[8] = { q0.x, q0.y, q1.x, q1.y, q2.x, q2.y, q3.x, q3.y };
        float4 k4 = *(const float4*)&KsT[h * 132 + cg * 4];
        u64 kb0 = bcast2(k4.x), kb1 = bcast2(k4.y), kb2 = bcast2(k4.z), kb3 = bcast2(k4.w);
#pragma unroll
        for (int ip = 0; ip < 8; ip++) {
            ffma2(S.u[ip][0], qb[ip], kb0);
            ffma2(S.u[ip][1], qb[ip], kb1);
            ffma2(S.u[ip][2], qb[ip], kb2);
            ffma2(S.u[ip][3], qb[ip], kb3);
        }
    }

    // ---- row softmax; full-warp reduction (32 cg lanes hold one row) ----
#pragma unroll
    for (int r = 0; r < 16; r++) {
        float m = ACC_F(S, r, 0);
        m = fmaxf(m, ACC_F(S, r, 1));
        m = fmaxf(m, ACC_F(S, r, 2));
        m = fmaxf(m, ACC_F(S, r, 3));
#pragma unroll
        for (int o = 16; o >= 1; o >>= 1)
            m = fmaxf(m, __shfl_xor_sync(0xffffffffu, m, o));
        float s0 = __expf(ACC_F(S, r, 0) - m);
        float s1 = __expf(ACC_F(S, r, 1) - m);
        float s2 = __expf(ACC_F(S, r, 2) - m);
        float s3 = __expf(ACC_F(S, r, 3) - m);
        float ss = (s0 + s1) + (s2 + s3);
#pragma unroll
        for (int o = 16; o >= 1; o >>= 1)
            ss += __shfl_xor_sync(0xffffffffu, ss, o);
        float rinv = 1.0f / ss;
        ACC_F(S, r, 0) = s0 * rinv;
        ACC_F(S, r, 1) = s1 * rinv;
        ACC_F(S, r, 2) = s2 * rinv;
        ACC_F(S, r, 3) = s3 * rinv;
    }

    // all QsT reads of this half done -> safe to overwrite with P^T
    asm volatile("bar.sync %0, %1;" :: "r"(half + 1), "n"(128) : "memory");

    // write P^T: Qh[col][row], column-staggered to spread banks
#pragma unroll
    for (int j = 0; j < 4; j++) {
        int jc = (j + cg) & 3;
        int col = cg * 4 + jc;
#pragma unroll
        for (int m4 = 0; m4 < 4; m4++) {
            float4 v = make_float4(ACC_F(S, m4 * 4 + 0, jc), ACC_F(S, m4 * 4 + 1, jc),
                                   ACC_F(S, m4 * 4 + 2, jc), ACC_F(S, m4 * 4 + 3, jc));
            *(float4*)&Qh[col * 68 + rg * 16 + m4 * 4] = v;
        }
    }

    asm volatile("bar.sync %0, %1;" :: "r"(half + 1), "n"(128) : "memory");

    // ---- O = P @ V (contraction over k) ----
    union { u64 u[8][4]; float f[64]; } O;
#pragma unroll
    for (int ip = 0; ip < 8; ip++)
#pragma unroll
        for (int j = 0; j < 4; j++) O.u[ip][j] = 0ull;

#pragma unroll 2
    for (int k = 0; k < 128; k++) {
        const ulonglong2* pp = (const ulonglong2*)&Qh[k * 68 + rg * 16];
        ulonglong2 p0 = pp[0], p1 = pp[1], p2 = pp[2], p3 = pp[3];
        u64 pb[8] = { p0.x, p0.y, p1.x, p1.y, p2.x, p2.y, p3.x, p3.y };
        float4 v4 = *(const float4*)&Vs[k * 128 + cg * 4];
        u64 vb0 = bcast2(v4.x), vb1 = bcast2(v4.y), vb2 = bcast2(v4.z), vb3 = bcast2(v4.w);
#pragma unroll
        for (int ip = 0; ip < 8; ip++) {
            ffma2(O.u[ip][0], pb[ip], vb0);
            ffma2(O.u[ip][1], pb[ip], vb1);
            ffma2(O.u[ip][2], pb[ip], vb2);
            ffma2(O.u[ip][3], pb[ip], vb3);
        }
    }

#pragma unroll
    for (int r = 0; r < 16; r++) {
        int w = half * 64 + rg * 16 + r;
        float4 v = make_float4(ACC_F(O, r, 0), ACC_F(O, r, 1), ACC_F(O, r, 2), ACC_F(O, r, 3));
        *(float4*)&Og[w * 128 + cg * 4] = v;
    }
}

// ---------------------------------------------------------------------------
// Kernel 3: output 1x1 conv. out[64,N] = Wo[64,64] @ O[64,N] + bo
// 256 threads, 256 positions per CTA. rg = tid>>6 (4 x 16 rows), cg = tid&63.
// ---------------------------------------------------------------------------
__global__ __launch_bounds__(256) void out_kernel(
    const float* __restrict__ wo, const float* __restrict__ bo,
    float* __restrict__ out)
{
    extern __shared__ float sm[];
    float* WsT  = sm;              // [64][68]
    float* bias = WsT + 64 * 68;   // 64
    float* Xs   = bias + 64;       // [64][260]

    const int tid = threadIdx.x;
    for (int i = tid; i < 4096; i += 256) {
        int o = i >> 6, c = i & 63;
        WsT[c * 68 + o] = wo[i];
    }
    if (tid < 64) bias[tid] = bo[tid];
    const int p0 = blockIdx.x << 8;
    for (int i = tid; i < 16384; i += 256) {
        int c = i >> 8, p = i & 255;
        Xs[c * 260 + p] = g_o[c * NPOS + p0 + p];
    }
    __syncthreads();

    const int rg = tid >> 6;   // 0..3  -> rows rg*16..+15
    const int cg = tid & 63;   // 0..63 -> cols cg*4..+3

    union { u64 u[8][4]; float f[64]; } A;
#pragma unroll
    for (int ip = 0; ip < 8; ip++)
#pragma unroll
        for (int j = 0; j < 4; j++) A.u[ip][j] = 0ull;

#pragma unroll 2
    for (int c = 0; c < 64; c++) {
        const ulonglong2* wp = (const ulonglong2*)&WsT[c * 68 + rg * 16];
        ulonglong2 w0 = wp[0], w1 = wp[1], w2 = wp[2], w3 = wp[3];
        u64 wb[8] = { w0.x, w0.y, w1.x, w1.y, w2.x, w2.y, w3.x, w3.y };
        float4 x4 = *(const float4*)&Xs[c * 260 + cg * 4];
        u64 xb0 = bcast2(x4.x), xb1 = bcast2(x4.y), xb2 = bcast2(x4.z), xb3 = bcast2(x4.w);
#pragma unroll
        for (int ip = 0; ip < 8; ip++) {
            ffma2(A.u[ip][0], wb[ip], xb0);
            ffma2(A.u[ip][1], wb[ip], xb1);
            ffma2(A.u[ip][2], wb[ip], xb2);
            ffma2(A.u[ip][3], wb[ip], xb3);
        }
    }

#pragma unroll
    for (int r = 0; r < 16; r++) {
        int o = rg * 16 + r;
        float bb = bias[o];
        float4 v = make_float4(ACC_F(A, r, 0) + bb, ACC_F(A, r, 1) + bb,
                               ACC_F(A, r, 2) + bb, ACC_F(A, r, 3) + bb);
        *(float4*)&out[(size_t)o * NPOS + p0 + cg * 4] = v;
    }
}

// ---------------------------------------------------------------------------
extern "C" void kernel_launch(void* const* d_in, const int* in_sizes, int n_in,
                              void* d_out, int out_size)
{
    const float* x  = (const float*)d_in[0];
    const float* wq = (const float*)d_in[1];
    const float* bq = (const float*)d_in[2];
    const float* wk = (const float*)d_in[3];
    const float* bk = (const float*)d_in[4];
    const float* wv = (const float*)d_in[5];
    const float* bv = (const float*)d_in[6];
    const float* wo = (const float*)d_in[7];
    const float* bo = (const float*)d_in[8];
    float* out = (float*)d_out;

    const int smem1 = (64 * 196 + 192 + 64 * 132) * 4;                    // 84736
    const int smem2 = (128 * 132 + 128 * 128 + 2 * 128 * 68) * 4;         // 202752
    const int smem3 = (64 * 68 + 64 + 64 * 260) * 4;                      // 84224

    cudaFuncSetAttribute(qkv_kernel,  cudaFuncAttributeMaxDynamicSharedMemorySize, smem1);
    cudaFuncSetAttribute(attn_kernel, cudaFuncAttributeMaxDynamicSharedMemorySize, smem2);
    cudaFuncSetAttribute(out_kernel,  cudaFuncAttributeMaxDynamicSharedMemorySize, smem3);

    qkv_kernel<<<NPOS / 128, 384, smem1>>>(x, wq, bq, wk, bk, wv, bv);
    attn_kernel<<<64 * 48, 256, smem2>>>();
    out_kernel<<<NPOS / 256, 256, smem3>>>(wo, bo, out);
}